// round 1
// baseline (speedup 1.0000x reference)
#include <cuda_runtime.h>
#include <math.h>

// SupConLoss: N=8192 embeddings (C=128, L2-normalized), logits = X X^T / T.
// Fused syrk + exp/mask epilogue; never materializes the 8192x8192 matrix.

#define Nn 8192
#define Cc 128
#define BM 64
#define BN 64
#define NTC (Nn/BN)                  // 128 col tiles
#define TOT_TILES ((Nn/BM)*(Nn/BN))  // 16384
#define NBLK 444                     // 148 SMs * 3 CTAs/SM -> one wave
#define INV_T 14.285714285714285714f

// Scratch (device globals: no allocation allowed in kernel_launch)
__device__ float g_XT[Cc * Nn];   // k-major features, 4 MB (fits L2)
__device__ float g_S[Nn];         // sum_{j!=i} exp(logit_ij)
__device__ float g_P[Nn];         // sum_{j!=i, same label} raw dot (scaled later)
__device__ int   g_lab[Nn];
__device__ int   g_hist[4];

__global__ void k_zero() {
    int i = blockIdx.x * 256 + threadIdx.x;
    if (i < Nn) { g_S[i] = 0.f; g_P[i] = 0.f; }
    if (i < 4) g_hist[i] = 0;
}

// features [B,V,C,H,W] f32 -> g_XT[c][n], n = ((v*B+b)*H+h)*W+w.
// Coalesced float4 read and write per (c, v*B+b) plane.
__global__ void k_repack(const float* __restrict__ f) {
    int idx = blockIdx.x * 256 + threadIdx.x;   // 262144 total
    int q  = idx & 255;        // float4 index within the 1024-elem HW plane
    int t  = idx >> 8;
    int vb = t & 7;            // vb = v*B + b
    int c  = t >> 3;
    int v  = vb >> 2, b = vb & 3;
    // features stride: b:262144  v:131072  c:1024 floats
    float4 val = ((const float4*)f)[b * 65536 + v * 32768 + c * 256 + q];
    ((float4*)g_XT)[c * 2048 + vb * 256 + q] = val;
}

// labels [B,V,H,W] i32 -> g_lab[n] + histogram
__global__ void k_lab(const int* __restrict__ labels) {
    int n = blockIdx.x * 256 + threadIdx.x;
    if (n >= Nn) return;
    int vb = n >> 10;
    int v = vb >> 2, b = vb & 3;
    int L = labels[b * 2048 + v * 1024 + (n & 1023)];
    g_lab[n] = L;
    atomicAdd(&g_hist[L], 1);
}

// Main fused syrk+epilogue. 256 threads (16x16), 4x4 microtile.
// Persistent static split of 16384 tiles over 444 blocks; contiguous tile
// ranges keep the A (row) tile resident across the j sweep.
__global__ __launch_bounds__(256, 3) void k_main() {
    extern __shared__ float sm[];
    float* As = sm;                    // [128][64], k-major
    float* Bs = sm + Cc * BM;          // [128][64], k-major
    int*  labB = (int*)(sm + 2 * Cc * BM);

    int tid = threadIdx.x;
    int tx = tid & 15, ty = tid >> 4;

    int t0 = (int)(((long long)blockIdx.x       * TOT_TILES) / NBLK);
    int t1 = (int)(((long long)(blockIdx.x + 1) * TOT_TILES) / NBLK);

    int curRow = -1;
    float Sl[4] = {0.f, 0.f, 0.f, 0.f};
    float Pl[4] = {0.f, 0.f, 0.f, 0.f};
    int labR[4];

    for (int t = t0; t < t1; t++) {
        int rt = t / NTC, ct = t % NTC;   // NTC power of two -> shifts
        int row0 = rt * BM, col0 = ct * BN;

        __syncthreads();  // previous tile's smem consumers done

        if (rt != curRow) {
            if (curRow >= 0) {
                // flush per-row partials: reduce across the 16 tx lanes
                #pragma unroll
                for (int m = 0; m < 4; m++) {
                    float s = Sl[m], p = Pl[m];
                    #pragma unroll
                    for (int o = 8; o; o >>= 1) {
                        s += __shfl_xor_sync(0xffffffffu, s, o);
                        p += __shfl_xor_sync(0xffffffffu, p, o);
                    }
                    if (tx == 0) {
                        int r = curRow * BM + ty * 4 + m;
                        atomicAdd(&g_S[r], s);
                        atomicAdd(&g_P[r], p);
                    }
                    Sl[m] = 0.f; Pl[m] = 0.f;
                }
            }
            // load A tile (k-major, coalesced gmem, conflict-free STS.128)
            #pragma unroll
            for (int it = 0; it < 8; it++) {
                int i = it * 256 + tid;
                int k = i >> 4, q = i & 15;
                float4 v = ((const float4*)g_XT)[k * 2048 + (row0 >> 2) + q];
                *(float4*)&As[k * BM + q * 4] = v;
            }
            #pragma unroll
            for (int m = 0; m < 4; m++) labR[m] = g_lab[row0 + ty * 4 + m];
            curRow = rt;
        }

        // load B tile + column labels
        #pragma unroll
        for (int it = 0; it < 8; it++) {
            int i = it * 256 + tid;
            int k = i >> 4, q = i & 15;
            float4 v = ((const float4*)g_XT)[k * 2048 + (col0 >> 2) + q];
            *(float4*)&Bs[k * BN + q * 4] = v;
        }
        if (tid < BN) labB[tid] = g_lab[col0 + tid];
        __syncthreads();

        // 4x4 microtile over K=128; LDS.128 on both operands, conflict-free
        float acc[4][4];
        #pragma unroll
        for (int m = 0; m < 4; m++)
            #pragma unroll
            for (int n = 0; n < 4; n++) acc[m][n] = 0.f;

        #pragma unroll 8
        for (int k = 0; k < Cc; k++) {
            float4 a = *(const float4*)&As[k * BM + ty * 4];
            float4 b = *(const float4*)&Bs[k * BN + tx * 4];
            float av[4] = {a.x, a.y, a.z, a.w};
            float bv[4] = {b.x, b.y, b.z, b.w};
            #pragma unroll
            for (int m = 0; m < 4; m++)
                #pragma unroll
                for (int n = 0; n < 4; n++)
                    acc[m][n] = fmaf(av[m], bv[n], acc[m][n]);
        }

        // epilogue: S += exp(dot/T) (j!=i); P += raw dot (same label, j!=i)
        int lj[4];
        #pragma unroll
        for (int n = 0; n < 4; n++) lj[n] = labB[tx * 4 + n];
        int gi0 = row0 + ty * 4, gj0 = col0 + tx * 4;
        #pragma unroll
        for (int m = 0; m < 4; m++) {
            int gi = gi0 + m;
            #pragma unroll
            for (int n = 0; n < 4; n++) {
                int gj = gj0 + n;
                float v = acc[m][n];
                if (gi != gj) {
                    Sl[m] += __expf(v * INV_T);
                    if (labR[m] == lj[n]) Pl[m] += v;
                }
            }
        }
    }

    if (curRow >= 0) {
        #pragma unroll
        for (int m = 0; m < 4; m++) {
            float s = Sl[m], p = Pl[m];
            #pragma unroll
            for (int o = 8; o; o >>= 1) {
                s += __shfl_xor_sync(0xffffffffu, s, o);
                p += __shfl_xor_sync(0xffffffffu, p, o);
            }
            if (tx == 0) {
                int r = curRow * BM + ty * 4 + m;
                atomicAdd(&g_S[r], s);
                atomicAdd(&g_P[r], p);
            }
        }
    }
}

__global__ void k_final(float* __restrict__ out) {
    __shared__ float shL[256], shW[256];
    int tid = threadIdx.x;
    float sl = 0.f, sw = 0.f;
    for (int i = tid; i < Nn; i += 256) {
        int L = g_lab[i];
        if (L != 0) {
            float cnt = (float)(g_hist[L] - 1);
            sl += logf(g_S[i]) - (g_P[i] * INV_T) / cnt;
            sw += 1.f;
        }
    }
    shL[tid] = sl; shW[tid] = sw;
    __syncthreads();
    for (int o = 128; o; o >>= 1) {
        if (tid < o) { shL[tid] += shL[tid + o]; shW[tid] += shW[tid + o]; }
        __syncthreads();
    }
    if (tid == 0) out[0] = shL[0] / shW[0];
}

extern "C" void kernel_launch(void* const* d_in, const int* in_sizes, int n_in,
                              void* d_out, int out_size) {
    (void)in_sizes; (void)n_in; (void)out_size;
    const float* feats  = (const float*)d_in[0];
    const int*   labels = (const int*)d_in[1];
    float*       out    = (float*)d_out;

    // 64.25 KB dynamic smem (> 48 KB static limit). Idempotent; first
    // (non-captured) correctness call sets it so capture-time calls are moot.
    cudaFuncSetAttribute(k_main, cudaFuncAttributeMaxDynamicSharedMemorySize,
                         2 * Cc * BM * (int)sizeof(float) + BN * (int)sizeof(int));

    k_zero<<<32, 256>>>();
    k_repack<<<1024, 256>>>(feats);
    k_lab<<<32, 256>>>(labels);
    k_main<<<NBLK, 256, 2 * Cc * BM * sizeof(float) + BN * sizeof(int)>>>();
    k_final<<<1, 256>>>(out);
}

// round 2
// speedup vs baseline: 1.0004x; 1.0004x over previous
#include <cuda_runtime.h>
#include <math.h>

// SupConLoss: N=8192 embeddings (C=128, L2-normalized), logits = X X^T / T.
// Fused syrk + exp/mask epilogue; never materializes the 8192x8192 matrix.

#define Nn 8192
#define Cc 128
#define BM 64
#define BN 64
#define NTC (Nn/BN)                  // 128 col tiles
#define TOT_TILES ((Nn/BM)*(Nn/BN))  // 16384
#define NBLK 444                     // 148 SMs * 3 CTAs/SM -> one wave
#define INV_T 14.285714285714285714f

// Scratch (device globals: no allocation allowed in kernel_launch)
__device__ float g_XT[Cc * Nn];   // k-major features, 4 MB (fits L2)
__device__ float g_S[Nn];         // sum_{j!=i} exp(logit_ij)
__device__ float g_P[Nn];         // sum_{j!=i, same label} raw dot (scaled later)
__device__ int   g_lab[Nn];
__device__ int   g_hist[4];

__global__ void k_zero() {
    int i = blockIdx.x * 256 + threadIdx.x;
    if (i < Nn) { g_S[i] = 0.f; g_P[i] = 0.f; }
    if (i < 4) g_hist[i] = 0;
}

// features [B,V,C,H,W] f32 -> g_XT[c][n], n = ((v*B+b)*H+h)*W+w.
// Coalesced float4 read and write per (c, v*B+b) plane.
__global__ void k_repack(const float* __restrict__ f) {
    int idx = blockIdx.x * 256 + threadIdx.x;   // 262144 total
    int q  = idx & 255;        // float4 index within the 1024-elem HW plane
    int t  = idx >> 8;
    int vb = t & 7;            // vb = v*B + b
    int c  = t >> 3;
    int v  = vb >> 2, b = vb & 3;
    // features stride: b:262144  v:131072  c:1024 floats
    float4 val = ((const float4*)f)[b * 65536 + v * 32768 + c * 256 + q];
    ((float4*)g_XT)[c * 2048 + vb * 256 + q] = val;
}

// labels [B,V,H,W] i32 -> g_lab[n] + histogram
__global__ void k_lab(const int* __restrict__ labels) {
    int n = blockIdx.x * 256 + threadIdx.x;
    if (n >= Nn) return;
    int vb = n >> 10;
    int v = vb >> 2, b = vb & 3;
    int L = labels[b * 2048 + v * 1024 + (n & 1023)];
    g_lab[n] = L;
    atomicAdd(&g_hist[L], 1);
}

// Main fused syrk+epilogue. 256 threads (16x16), 4x4 microtile.
// Persistent static split of 16384 tiles over 444 blocks; contiguous tile
// ranges keep the A (row) tile resident across the j sweep.
__global__ __launch_bounds__(256, 3) void k_main() {
    extern __shared__ float sm[];
    float* As = sm;                    // [128][64], k-major
    float* Bs = sm + Cc * BM;          // [128][64], k-major
    int*  labB = (int*)(sm + 2 * Cc * BM);

    int tid = threadIdx.x;
    int tx = tid & 15, ty = tid >> 4;

    int t0 = (int)(((long long)blockIdx.x       * TOT_TILES) / NBLK);
    int t1 = (int)(((long long)(blockIdx.x + 1) * TOT_TILES) / NBLK);

    int curRow = -1;
    float Sl[4] = {0.f, 0.f, 0.f, 0.f};
    float Pl[4] = {0.f, 0.f, 0.f, 0.f};
    int labR[4];

    for (int t = t0; t < t1; t++) {
        int rt = t / NTC, ct = t % NTC;   // NTC power of two -> shifts
        int row0 = rt * BM, col0 = ct * BN;

        __syncthreads();  // previous tile's smem consumers done

        if (rt != curRow) {
            if (curRow >= 0) {
                // flush per-row partials: reduce across the 16 tx lanes
                #pragma unroll
                for (int m = 0; m < 4; m++) {
                    float s = Sl[m], p = Pl[m];
                    #pragma unroll
                    for (int o = 8; o; o >>= 1) {
                        s += __shfl_xor_sync(0xffffffffu, s, o);
                        p += __shfl_xor_sync(0xffffffffu, p, o);
                    }
                    if (tx == 0) {
                        int r = curRow * BM + ty * 4 + m;
                        atomicAdd(&g_S[r], s);
                        atomicAdd(&g_P[r], p);
                    }
                    Sl[m] = 0.f; Pl[m] = 0.f;
                }
            }
            // load A tile (k-major, coalesced gmem, conflict-free STS.128)
            #pragma unroll
            for (int it = 0; it < 8; it++) {
                int i = it * 256 + tid;
                int k = i >> 4, q = i & 15;
                float4 v = ((const float4*)g_XT)[k * 2048 + (row0 >> 2) + q];
                *(float4*)&As[k * BM + q * 4] = v;
            }
            #pragma unroll
            for (int m = 0; m < 4; m++) labR[m] = g_lab[row0 + ty * 4 + m];
            curRow = rt;
        }

        // load B tile + column labels
        #pragma unroll
        for (int it = 0; it < 8; it++) {
            int i = it * 256 + tid;
            int k = i >> 4, q = i & 15;
            float4 v = ((const float4*)g_XT)[k * 2048 + (col0 >> 2) + q];
            *(float4*)&Bs[k * BN + q * 4] = v;
        }
        if (tid < BN) labB[tid] = g_lab[col0 + tid];
        __syncthreads();

        // 4x4 microtile over K=128; LDS.128 on both operands, conflict-free
        float acc[4][4];
        #pragma unroll
        for (int m = 0; m < 4; m++)
            #pragma unroll
            for (int n = 0; n < 4; n++) acc[m][n] = 0.f;

        #pragma unroll 8
        for (int k = 0; k < Cc; k++) {
            float4 a = *(const float4*)&As[k * BM + ty * 4];
            float4 b = *(const float4*)&Bs[k * BN + tx * 4];
            float av[4] = {a.x, a.y, a.z, a.w};
            float bv[4] = {b.x, b.y, b.z, b.w};
            #pragma unroll
            for (int m = 0; m < 4; m++)
                #pragma unroll
                for (int n = 0; n < 4; n++)
                    acc[m][n] = fmaf(av[m], bv[n], acc[m][n]);
        }

        // epilogue: S += exp(dot/T) (j!=i); P += raw dot (same label, j!=i)
        int lj[4];
        #pragma unroll
        for (int n = 0; n < 4; n++) lj[n] = labB[tx * 4 + n];
        int gi0 = row0 + ty * 4, gj0 = col0 + tx * 4;
        #pragma unroll
        for (int m = 0; m < 4; m++) {
            int gi = gi0 + m;
            #pragma unroll
            for (int n = 0; n < 4; n++) {
                int gj = gj0 + n;
                float v = acc[m][n];
                if (gi != gj) {
                    Sl[m] += __expf(v * INV_T);
                    if (labR[m] == lj[n]) Pl[m] += v;
                }
            }
        }
    }

    if (curRow >= 0) {
        #pragma unroll
        for (int m = 0; m < 4; m++) {
            float s = Sl[m], p = Pl[m];
            #pragma unroll
            for (int o = 8; o; o >>= 1) {
                s += __shfl_xor_sync(0xffffffffu, s, o);
                p += __shfl_xor_sync(0xffffffffu, p, o);
            }
            if (tx == 0) {
                int r = curRow * BM + ty * 4 + m;
                atomicAdd(&g_S[r], s);
                atomicAdd(&g_P[r], p);
            }
        }
    }
}

__global__ void k_final(float* __restrict__ out) {
    __shared__ float shL[256], shW[256];
    int tid = threadIdx.x;
    float sl = 0.f, sw = 0.f;
    for (int i = tid; i < Nn; i += 256) {
        int L = g_lab[i];
        if (L != 0) {
            float cnt = (float)(g_hist[L] - 1);
            sl += logf(g_S[i]) - (g_P[i] * INV_T) / cnt;
            sw += 1.f;
        }
    }
    shL[tid] = sl; shW[tid] = sw;
    __syncthreads();
    for (int o = 128; o; o >>= 1) {
        if (tid < o) { shL[tid] += shL[tid + o]; shW[tid] += shW[tid + o]; }
        __syncthreads();
    }
    if (tid == 0) out[0] = shL[0] / shW[0];
}

extern "C" void kernel_launch(void* const* d_in, const int* in_sizes, int n_in,
                              void* d_out, int out_size) {
    (void)in_sizes; (void)n_in; (void)out_size;
    const float* feats  = (const float*)d_in[0];
    const int*   labels = (const int*)d_in[1];
    float*       out    = (float*)d_out;

    // 64.25 KB dynamic smem (> 48 KB static limit). Idempotent; first
    // (non-captured) correctness call sets it so capture-time calls are moot.
    cudaFuncSetAttribute(k_main, cudaFuncAttributeMaxDynamicSharedMemorySize,
                         2 * Cc * BM * (int)sizeof(float) + BN * (int)sizeof(int));

    k_zero<<<32, 256>>>();
    k_repack<<<1024, 256>>>(feats);
    k_lab<<<32, 256>>>(labels);
    k_main<<<NBLK, 256, 2 * Cc * BM * sizeof(float) + BN * sizeof(int)>>>();
    k_final<<<1, 256>>>(out);
}

// round 6
// speedup vs baseline: 3.8782x; 3.8766x over previous
#include <cuda_runtime.h>
#include <cuda_bf16.h>
#include <cstdint>

// SupConLoss: N=8192 embeddings (C=128, L2-normalized), logits = X X^T / T.
// tcgen05 bf16 hi/lo-split syrk + fused exp/mask epilogue (serial, example-
// faithful shape), with runtime-dispatched fp32 SIMT fallback (proven 454us).

#define Nn 8192
#define TILE 128
#define NB 64
#define TOT_TILES (NB*NB)            // 4096 128x128 tiles
#define NBLK_TC 148
#define INV_T 14.285714285714285714f
#define EX2C 20.60992915555662f      // INV_T * log2(e)

// fp32 fallback tiling
#define BM 64
#define BN 64
#define NTC_F (Nn/BN)
#define TOT_TILES_F ((Nn/BM)*(Nn/BN))
#define NBLK_F 444

// ---- does this compilation pass have tcgen05? ----
#if !defined(__CUDA_ARCH__)
#  define TC_OK 1   /* host pass */
#elif defined(__CUDA_ARCH_FEAT_SM103_ALL) || defined(__CUDA_ARCH_FEAT_SM100_ALL) || \
      defined(__CUDA_ARCH_FEAT_SM101_ALL) || defined(__CUDA_ARCH_FAMILY_SPECIFIC__) || \
      defined(__CUDA_ARCH_SPECIFIC__)
#  define TC_OK 1
#else
#  define TC_OK 0
#endif

// ---- scratch (device globals; no allocation allowed) ----
__device__ uint4 g_hi[Nn * 128 / 8];   // 2 MB blocked SW128-swizzled bf16 tiles
__device__ uint4 g_lo[Nn * 128 / 8];
__device__ float g_XT[128 * Nn];       // 4 MB k-major fp32 (fallback)
__device__ float g_S[Nn];
__device__ float g_P[Nn];
__device__ int   g_lab[Nn];
__device__ int   g_hist[4];
__device__ int   g_tc;                 // 1 iff tcgen05 path is live

// ---- PTX helpers ----
__device__ __forceinline__ uint32_t smem_u32(const void* p) {
    uint32_t a;
    asm("{ .reg .u64 t; cvta.to.shared.u64 t, %1; cvt.u32.u64 %0, t; }" : "=r"(a) : "l"(p));
    return a;
}
__device__ __forceinline__ uint32_t elect_one() {
    uint32_t pred;
    asm volatile("{ .reg .pred p; elect.sync _|p, 0xFFFFFFFF; selp.b32 %0, 1, 0, p; }" : "=r"(pred));
    return pred;
}
#define MBARRIER_INIT(mb, c) \
    asm volatile("mbarrier.init.shared.b64 [%0], %1;" :: "r"((uint32_t)(mb)), "r"((uint32_t)(c)) : "memory")
#define MBARRIER_INVAL(mb) \
    asm volatile("mbarrier.inval.shared.b64 [%0];" :: "r"((uint32_t)(mb)) : "memory")
#define MBARRIER_WAIT_PARITY(mb, ph) do {                                          \
    uint32_t _m = (uint32_t)(mb), _p = (uint32_t)(ph), _d;                         \
    asm volatile("{ .reg .pred p; mbarrier.try_wait.parity.acquire.cta.shared::cta.b64 p, [%1], %2; selp.b32 %0, 1, 0, p; }" \
                 : "=r"(_d) : "r"(_m), "r"(_p) : "memory");                        \
    if (!_d) {                                                                     \
        asm volatile("{ .reg .pred P1; WL_%=: mbarrier.try_wait.parity.acquire.cta.shared::cta.b64 P1, [%0], %1, 0x989680; @P1 bra.uni WD_%=; bra.uni WL_%=; WD_%=: }" \
                     :: "r"(_m), "r"(_p) : "memory");                              \
    } } while (0)

#if TC_OK
#define TCGEN05_ALLOC(sa, n) \
    asm volatile("tcgen05.alloc.cta_group::1.sync.aligned.shared::cta.b32 [%0], %1;" \
                 :: "r"((uint32_t)(sa)), "r"((uint32_t)(n)) : "memory")
#define TCGEN05_DEALLOC(t, n) \
    asm volatile("tcgen05.dealloc.cta_group::1.sync.aligned.b32 %0, %1;" :: "r"(t), "r"((uint32_t)(n)))
#define TCGEN05_RELINQ() \
    asm volatile("tcgen05.relinquish_alloc_permit.cta_group::1.sync.aligned;")
#define TCGEN05_COMMIT(mb) \
    asm volatile("tcgen05.commit.cta_group::1.mbarrier::arrive::one.shared::cluster.b64 [%0];" \
                 :: "r"((uint32_t)(mb)) : "memory")
#define TCGEN05_WAIT_LD()      asm volatile("tcgen05.wait::ld.sync.aligned;" ::: "memory")
#define TCGEN05_FENCE_BEFORE() asm volatile("tcgen05.fence::before_thread_sync;" ::: "memory")
#define TCGEN05_FENCE_AFTER()  asm volatile("tcgen05.fence::after_thread_sync;" ::: "memory")
#define TCGEN05_LD_X32(r, a) \
    asm volatile("tcgen05.ld.sync.aligned.32x32b.x32.b32 " \
        "{%0,%1,%2,%3,%4,%5,%6,%7,%8,%9,%10,%11,%12,%13,%14,%15," \
        "%16,%17,%18,%19,%20,%21,%22,%23,%24,%25,%26,%27,%28,%29,%30,%31}, [%32];" \
        : "=r"((r)[0]),"=r"((r)[1]),"=r"((r)[2]),"=r"((r)[3]),"=r"((r)[4]),"=r"((r)[5]),"=r"((r)[6]),"=r"((r)[7]), \
          "=r"((r)[8]),"=r"((r)[9]),"=r"((r)[10]),"=r"((r)[11]),"=r"((r)[12]),"=r"((r)[13]),"=r"((r)[14]),"=r"((r)[15]), \
          "=r"((r)[16]),"=r"((r)[17]),"=r"((r)[18]),"=r"((r)[19]),"=r"((r)[20]),"=r"((r)[21]),"=r"((r)[22]),"=r"((r)[23]), \
          "=r"((r)[24]),"=r"((r)[25]),"=r"((r)[26]),"=r"((r)[27]),"=r"((r)[28]),"=r"((r)[29]),"=r"((r)[30]),"=r"((r)[31]) \
        : "r"(a))

static constexpr uint64_t SMEM_DESC_BASE_SW128 =
    (uint64_t(2) << 61) | (uint64_t(1) << 46) | (uint64_t(64) << 32) | (uint64_t(1) << 16);
#define MAKE_DESC(addr) (SMEM_DESC_BASE_SW128 | ((uint64_t)((addr) >> 4) & 0x3FFF))

// SS cg1 bf16 MMA, fp32 accumulate. idesc: F32 d, BF16 a/b, M=128, N=128.
#define MMA_IDESC 0x08200490u
static __device__ __forceinline__ void mma_ss(uint32_t d, uint64_t a, uint64_t b, uint32_t en) {
    asm volatile("{ .reg .pred p; setp.ne.u32 p, %4, 0;\n\t"
        "tcgen05.mma.cta_group::1.kind::f16 [%0], %1, %2, %3, {%5,%5,%5,%5}, p; }"
        :: "r"(d), "l"(a), "l"(b), "r"(MMA_IDESC), "r"(en), "r"(0u) : "memory");
}
#endif  // TC_OK

// ---- smem layout (k_main_tc), bytes; tile bases 1024-aligned ----
#define OFF_AHI 0
#define OFF_ALO 32768
#define OFF_BHI 65536
#define OFF_BLO 98304
#define OFF_TP  131072
#define OFF_MB  131088
#define OFF_LAB 131104    // 128 ints
#define SMEM_SZ 131616

// ---- prologue kernels (arch-generic) ----
__global__ void k_probe() {
#if TC_OK
    g_tc = 1;
#else
    g_tc = 0;
#endif
}

__global__ void k_zero() {
    int i = blockIdx.x * 256 + threadIdx.x;
    if (i < Nn) { g_S[i] = 0.f; g_P[i] = 0.f; }
    if (i < 4) g_hist[i] = 0;
}

// fp32 [B=4,V=2,C=128,HW=1024] -> bf16 hi/lo in blocked SW128 tile format.
// Per 128-row band: 16 atom-rows x 2 atom-cols of 8x(64 bf16) SW128 atoms.
__global__ void k_prep(const float* __restrict__ f) {
    int idx = blockIdx.x * 256 + threadIdx.x;   // 524288
    int n = idx & 8191;
    int j = idx >> 13;
    int vb = n >> 10, hw = n & 1023;
    int v = vb >> 2, b = vb & 3;
    const float* base = f + b * 262144 + v * 131072 + hw;
    float x0 = base[(2 * j) * 1024];
    float x1 = base[(2 * j + 1) * 1024];
    __nv_bfloat16 h0 = __float2bfloat16(x0);
    __nv_bfloat16 h1 = __float2bfloat16(x1);
    __nv_bfloat16 l0 = __float2bfloat16(x0 - __bfloat162float(h0));
    __nv_bfloat16 l1 = __float2bfloat16(x1 - __bfloat162float(h1));
    uint32_t hp = (uint32_t)__bfloat16_as_ushort(h0) | ((uint32_t)__bfloat16_as_ushort(h1) << 16);
    uint32_t lp = (uint32_t)__bfloat16_as_ushort(l0) | ((uint32_t)__bfloat16_as_ushort(l1) << 16);
    int band = n >> 7, r = n & 127, k = 2 * j;
    int atom = (r >> 3) + (k >> 6) * 16;
    uint32_t byte = atom * 1024 + (r & 7) * 128 + (k & 63) * 2;
    uint32_t sw = byte ^ ((byte >> 3) & 0x70);  // SW128
    uint32_t w = band * 8192 + (sw >> 2);
    ((uint32_t*)g_hi)[w] = hp;
    ((uint32_t*)g_lo)[w] = lp;
}

// fp32 k-major repack (fallback path)
__global__ void k_repack(const float* __restrict__ f) {
    int idx = blockIdx.x * 256 + threadIdx.x;   // 262144
    int q  = idx & 255;
    int t  = idx >> 8;
    int vb = t & 7;
    int c  = t >> 3;
    int v  = vb >> 2, b = vb & 3;
    float4 val = ((const float4*)f)[b * 65536 + v * 32768 + c * 256 + q];
    ((float4*)g_XT)[c * 2048 + vb * 256 + q] = val;
}

__global__ void k_lab(const int* __restrict__ labels) {
    int n = blockIdx.x * 256 + threadIdx.x;
    if (n >= Nn) return;
    int vb = n >> 10;
    int v = vb >> 2, b = vb & 3;
    int L = labels[b * 2048 + v * 1024 + (n & 1023)];
    g_lab[n] = L;
    atomicAdd(&g_hist[L], 1);
}

// ---- tcgen05 main: 148 persistent CTAs, 8 warps, serial per tile ----
__global__ __launch_bounds__(256, 1) __cluster_dims__(1, 1, 1) void k_main_tc() {
#if TC_OK
    extern __shared__ char smc[];
    uint32_t sb = smem_u32(smc);
    int tid = threadIdx.x, wid = tid >> 5, lid = tid & 31;

    if (wid == 0) TCGEN05_ALLOC(sb + OFF_TP, 512);
    else          TCGEN05_RELINQ();
    __syncthreads();
    uint32_t tbase;
    asm volatile("ld.shared.b32 %0, [%1];" : "=r"(tbase) : "r"(sb + OFF_TP));
    if (tid == 0) MBARRIER_INIT(sb + OFF_MB, 1);
    __syncthreads();

    const uint32_t KOFF[8] = {0, 2, 4, 6, 1024, 1026, 1028, 1030};  // 16B units

    int t0 = (int)(((long long)blockIdx.x * TOT_TILES) / NBLK_TC);
    int t1 = (int)(((long long)(blockIdx.x + 1) * TOT_TILES) / NBLK_TC);
    int phase = 0, curA = -1;

    int sub = wid & 3, colh = wid >> 2;           // TMEM lane group / col half
    int row = sub * 32 + lid;

    for (int t = t0; t < t1; t++) {
        int rt = t >> 6, ct = t & 63;
        __syncthreads();   // previous tile's epilogue fully done; smem reusable

        if (rt != curA) {  // band change: reload A (rare; tiles are row-major)
            const uint4* sH = g_hi + rt * 2048;
            const uint4* sL = g_lo + rt * 2048;
            uint4* dH = (uint4*)(smc + OFF_AHI);
            uint4* dL = (uint4*)(smc + OFF_ALO);
            for (int i = tid; i < 2048; i += 256) { dH[i] = sH[i]; dL[i] = sL[i]; }
            curA = rt;
        }
        {
            const uint4* sH = g_hi + ct * 2048;
            const uint4* sL = g_lo + ct * 2048;
            uint4* dH = (uint4*)(smc + OFF_BHI);
            uint4* dL = (uint4*)(smc + OFF_BLO);
            for (int i = tid; i < 2048; i += 256) { dH[i] = sH[i]; dL[i] = sL[i]; }
            if (tid < 128) ((int*)(smc + OFF_LAB))[tid] = g_lab[ct * TILE + tid];
        }
        __syncthreads();

        if (wid == 0) {
            TCGEN05_FENCE_AFTER();
            if (elect_one()) {
                uint64_t aH = MAKE_DESC(sb + OFF_AHI);
                uint64_t aL = MAKE_DESC(sb + OFF_ALO);
                uint64_t bH = MAKE_DESC(sb + OFF_BHI);
                uint64_t bL = MAKE_DESC(sb + OFF_BLO);
                #pragma unroll
                for (int ks = 0; ks < 8; ks++) mma_ss(tbase, aH + KOFF[ks], bH + KOFF[ks], ks > 0);
                #pragma unroll
                for (int ks = 0; ks < 8; ks++) mma_ss(tbase, aH + KOFF[ks], bL + KOFF[ks], 1u);
                #pragma unroll
                for (int ks = 0; ks < 8; ks++) mma_ss(tbase, aL + KOFF[ks], bH + KOFF[ks], 1u);
                TCGEN05_COMMIT(sb + OFF_MB);
            }
        }

        // all threads wait for the MMA chain, then fused epilogue
        MBARRIER_WAIT_PARITY(sb + OFF_MB, phase);
        phase ^= 1;
        TCGEN05_FENCE_AFTER();

        int gi = rt * TILE + row;
        int labR = g_lab[gi];
        const int* labB = (const int*)(smc + OFF_LAB);
        float S = 0.f, P = 0.f;
        uint32_t d[32];
        #pragma unroll
        for (int half = 0; half < 2; half++) {
            TCGEN05_LD_X32(d, tbase + colh * 64 + half * 32);
            TCGEN05_WAIT_LD();
            int cbase = colh * 64 + half * 32;
            int jbase = ct * TILE + cbase;
            #pragma unroll
            for (int c = 0; c < 32; c++) {
                float v = __uint_as_float(d[c]);
                float e;
                asm("ex2.approx.ftz.f32 %0, %1;" : "=f"(e) : "f"(v * EX2C));
                if ((jbase + c) != gi) {
                    S += e;
                    if (labB[cbase + c] == labR) P += v;
                }
            }
        }
        TCGEN05_FENCE_BEFORE();
        atomicAdd(&g_S[gi], S);
        atomicAdd(&g_P[gi], P);
    }

    __syncthreads();
    if (tid == 0) MBARRIER_INVAL(sb + OFF_MB);
    __syncthreads();
    if (wid == 0) TCGEN05_DEALLOC(tbase, 512);
#endif  // TC_OK
}

// ---- fp32 SIMT fallback (proven R1 kernel); early-exits when tcgen05 live ----
__global__ __launch_bounds__(256, 3) void k_main_f32() {
    if (g_tc) return;
    extern __shared__ float sm[];
    float* As = sm;
    float* Bs = sm + 128 * BM;
    int*  labB = (int*)(sm + 2 * 128 * BM);

    int tid = threadIdx.x;
    int tx = tid & 15, ty = tid >> 4;

    int t0 = (int)(((long long)blockIdx.x       * TOT_TILES_F) / NBLK_F);
    int t1 = (int)(((long long)(blockIdx.x + 1) * TOT_TILES_F) / NBLK_F);

    int curRow = -1;
    float Sl[4] = {0.f, 0.f, 0.f, 0.f};
    float Pl[4] = {0.f, 0.f, 0.f, 0.f};
    int labR[4];

    for (int t = t0; t < t1; t++) {
        int rt = t / NTC_F, ct = t % NTC_F;
        int row0 = rt * BM, col0 = ct * BN;
        __syncthreads();
        if (rt != curRow) {
            if (curRow >= 0) {
                #pragma unroll
                for (int m = 0; m < 4; m++) {
                    float s = Sl[m], p = Pl[m];
                    #pragma unroll
                    for (int o = 8; o; o >>= 1) {
                        s += __shfl_xor_sync(0xffffffffu, s, o);
                        p += __shfl_xor_sync(0xffffffffu, p, o);
                    }
                    if (tx == 0) {
                        int r = curRow * BM + ty * 4 + m;
                        atomicAdd(&g_S[r], s);
                        atomicAdd(&g_P[r], p);
                    }
                    Sl[m] = 0.f; Pl[m] = 0.f;
                }
            }
            #pragma unroll
            for (int it = 0; it < 8; it++) {
                int i = it * 256 + tid;
                int k = i >> 4, q = i & 15;
                float4 v = ((const float4*)g_XT)[k * 2048 + (row0 >> 2) + q];
                *(float4*)&As[k * BM + q * 4] = v;
            }
            #pragma unroll
            for (int m = 0; m < 4; m++) labR[m] = g_lab[row0 + ty * 4 + m];
            curRow = rt;
        }
        #pragma unroll
        for (int it = 0; it < 8; it++) {
            int i = it * 256 + tid;
            int k = i >> 4, q = i & 15;
            float4 v = ((const float4*)g_XT)[k * 2048 + (col0 >> 2) + q];
            *(float4*)&Bs[k * BN + q * 4] = v;
        }
        if (tid < BN) labB[tid] = g_lab[col0 + tid];
        __syncthreads();

        float acc[4][4];
        #pragma unroll
        for (int m = 0; m < 4; m++)
            #pragma unroll
            for (int n = 0; n < 4; n++) acc[m][n] = 0.f;
        #pragma unroll 8
        for (int k = 0; k < 128; k++) {
            float4 a = *(const float4*)&As[k * BM + ty * 4];
            float4 b = *(const float4*)&Bs[k * BN + tx * 4];
            float av[4] = {a.x, a.y, a.z, a.w};
            float bv[4] = {b.x, b.y, b.z, b.w};
            #pragma unroll
            for (int m = 0; m < 4; m++)
                #pragma unroll
                for (int n = 0; n < 4; n++)
                    acc[m][n] = fmaf(av[m], bv[n], acc[m][n]);
        }
        int lj[4];
        #pragma unroll
        for (int n = 0; n < 4; n++) lj[n] = labB[tx * 4 + n];
        int gi0 = row0 + ty * 4, gj0 = col0 + tx * 4;
        #pragma unroll
        for (int m = 0; m < 4; m++) {
            int gi = gi0 + m;
            #pragma unroll
            for (int n = 0; n < 4; n++) {
                int gj = gj0 + n;
                float v = acc[m][n];
                if (gi != gj) {
                    Sl[m] += __expf(v * INV_T);
                    if (labR[m] == lj[n]) Pl[m] += v;
                }
            }
        }
    }
    if (curRow >= 0) {
        #pragma unroll
        for (int m = 0; m < 4; m++) {
            float s = Sl[m], p = Pl[m];
            #pragma unroll
            for (int o = 8; o; o >>= 1) {
                s += __shfl_xor_sync(0xffffffffu, s, o);
                p += __shfl_xor_sync(0xffffffffu, p, o);
            }
            if (tx == 0) {
                int r = curRow * BM + ty * 4 + m;
                atomicAdd(&g_S[r], s);
                atomicAdd(&g_P[r], p);
            }
        }
    }
}

__global__ void k_final(float* __restrict__ out) {
    __shared__ float shL[256], shW[256];
    int tid = threadIdx.x;
    float sl = 0.f, sw = 0.f;
    for (int i = tid; i < Nn; i += 256) {
        int L = g_lab[i];
        if (L != 0) {
            float cnt = (float)(g_hist[L] - 1);
            sl += logf(g_S[i]) - (g_P[i] * INV_T) / cnt;
            sw += 1.f;
        }
    }
    shL[tid] = sl; shW[tid] = sw;
    __syncthreads();
    for (int o = 128; o; o >>= 1) {
        if (tid < o) { shL[tid] += shL[tid + o]; shW[tid] += shW[tid + o]; }
        __syncthreads();
    }
    if (tid == 0) out[0] = shL[0] / shW[0];
}

extern "C" void kernel_launch(void* const* d_in, const int* in_sizes, int n_in,
                              void* d_out, int out_size) {
    (void)in_sizes; (void)n_in; (void)out_size;
    const float* feats  = (const float*)d_in[0];
    const int*   labels = (const int*)d_in[1];
    float*       out    = (float*)d_out;

    cudaFuncSetAttribute(k_main_tc, cudaFuncAttributeMaxDynamicSharedMemorySize, SMEM_SZ);
    cudaFuncSetAttribute(k_main_f32, cudaFuncAttributeMaxDynamicSharedMemorySize,
                         2 * 128 * BM * (int)sizeof(float) + BN * (int)sizeof(int));

    k_probe<<<1, 1>>>();
    k_zero<<<32, 256>>>();
    k_prep<<<2048, 256>>>(feats);
    k_repack<<<1024, 256>>>(feats);
    k_lab<<<32, 256>>>(labels);
    k_main_tc<<<NBLK_TC, 256, SMEM_SZ>>>();
    k_main_f32<<<NBLK_F, 256, 2 * 128 * BM * sizeof(float) + BN * sizeof(int)>>>();
    k_final<<<1, 256>>>(out);
}